// round 5
// baseline (speedup 1.0000x reference)
#include <cuda_runtime.h>
#include <cuda_bf16.h>

// Problem constants (fixed by the dataset: b=2, c=8, h=w=128, P=3, Wn=7)
#define IMG_H 128
#define IMG_W 128
#define NCH 8
#define NB 2
#define PL (IMG_H*IMG_W)

#define TY 8
#define TX 16
#define NPIX (TY*TX)           // 128 pixels per tile
#define NSLICE 4
#define NTHREADS (NPIX*NSLICE) // 512
#define HP 4                   // phi halo: window +-3 plus patch +-1
#define HG 3                   // g halo: window +-3
#define PH (TY + 2*HP)         // 16
#define PW (TX + 2*HP)         // 24
#define GH (TY + 2*HG)         // 14
#define GW (TX + 2*HG)         // 22
#define NPHI (PH*PW)           // 384
#define NG (GH*GW)             // 308

// Correlation map: tile dilated by 1 pixel (patch radius)
#define CW 18                  // TX + 2
#define CHh 10                 // TY + 2
#define CN (CHh*CW)            // 180 logical positions
#define CNP 184                // padded stride; Cs also doubles as merge scratch

// per-slice named barrier (4 consecutive warps = 128 threads)
#define BARS(id) asm volatile("bar.sync %0, %1;" :: "r"(id), "r"(128) : "memory")

__global__ __launch_bounds__(NTHREADS, 2)
void attn_slice_nb_kernel(const float* __restrict__ u,
                          const float* __restrict__ pan,
                          const float* __restrict__ Wphi,
                          const float* __restrict__ Wg,
                          float* __restrict__ out)
{
    // channel-plane layout: conflict-free 16B-stride LDS.128
    __shared__ __align__(16) float4 phiA[NPHI], phiB[NPHI];
    __shared__ __align__(16) float4 gA[NG],  gB[NG];
    __shared__ float Cs[NSLICE][7][CNP];        // per-slice row of 7 corr maps
    __shared__ float wphi_s[NCH*NCH];
    __shared__ float wg_s[NCH*NCH];

    const int tid  = threadIdx.x;
    const int bimg = blockIdx.z;
    const int y0   = blockIdx.y * TY;
    const int x0   = blockIdx.x * TX;

    if (tid < NCH*NCH)              wphi_s[tid] = Wphi[tid];
    else if (tid < 2*NCH*NCH)       wg_s[tid - NCH*NCH] = Wg[tid - NCH*NCH];
    __syncthreads();

    const float* panb = pan + (size_t)bimg * NCH * PL;
    const float* ub   = u   + (size_t)bimg * NCH * PL;

    // ---- fused prologue: 692 units (384 phi cells + 308 g cells) over 512 thr ----
    #pragma unroll
    for (int base = 0; base < NPHI + NG; base += NTHREADS) {
        const int i = base + tid;
        if (i < NPHI) {
            // phi0 = W_phi @ pan with +-4 halo (zero outside image)
            int r = i / PW, c = i % PW;
            int yy = y0 - HP + r, xx = x0 - HP + c;
            bool in = ((unsigned)yy < IMG_H) && ((unsigned)xx < IMG_W);
            float pv[NCH];
            #pragma unroll
            for (int ch = 0; ch < NCH; ch++)
                pv[ch] = in ? panb[ch*PL + yy*IMG_W + xx] : 0.f;
            float po[NCH];
            #pragma unroll
            for (int o = 0; o < NCH; o++) {
                float acc = 0.f;
                #pragma unroll
                for (int ci = 0; ci < NCH; ci++)
                    acc = fmaf(wphi_s[o*NCH+ci], pv[ci], acc);
                po[o] = acc;
            }
            phiA[i] = make_float4(po[0], po[1], po[2], po[3]);
            phiB[i] = make_float4(po[4], po[5], po[6], po[7]);
        } else if (i < NPHI + NG) {
            // g = W_g @ u with +-3 halo (zero outside image)
            int j = i - NPHI;
            int r = j / GW, c = j % GW;
            int yy = y0 - HG + r, xx = x0 - HG + c;
            bool in = ((unsigned)yy < IMG_H) && ((unsigned)xx < IMG_W);
            float uv[NCH];
            #pragma unroll
            for (int ch = 0; ch < NCH; ch++)
                uv[ch] = in ? ub[ch*PL + yy*IMG_W + xx] : 0.f;
            float go[NCH];
            #pragma unroll
            for (int o = 0; o < NCH; o++) {
                float acc = 0.f;
                #pragma unroll
                for (int ci = 0; ci < NCH; ci++)
                    acc = fmaf(wg_s[o*NCH+ci], uv[ci], acc);
                go[o] = acc;
            }
            gA[j] = make_float4(go[0], go[1], go[2], go[3]);
            gB[j] = make_float4(go[4], go[5], go[6], go[7]);
        }
    }
    __syncthreads();

    const int px    = tid & (NPIX-1);      // pixel within tile
    const int slice = tid >> 7;            // 0..3
    const int bar   = slice + 1;           // named barrier id for this slice
    const int ty = px / TX, tx = px % TX;
    const int gy = y0 + ty, gx = x0 + tx;

    // correlation positions handled by this thread (within its slice)
    const int p0    = px;                            // 0..127
    const int cell0 = (p0/CW + 3) * PW + (p0%CW + 3);
    const float4 v0a = phiA[cell0];
    const float4 v0b = phiB[cell0];
    const bool has1 = (px < CN - NPIX);              // px < 52
    const int p1    = px + NPIX;
    const int cell1 = (p1/CW + 3) * PW + (p1%CW + 3);
    float4 v1a = make_float4(0,0,0,0), v1b = make_float4(0,0,0,0);
    if (has1) { v1a = phiA[cell1]; v1b = phiB[cell1]; }

    // partial online softmax over this slice's dy rows
    float m = -3.4e38f, ssum = 0.f;
    float o0x=0.f,o0y=0.f,o0z=0.f,o0w=0.f;
    float o1x=0.f,o1y=0.f,o1z=0.f,o1w=0.f;

    #pragma unroll
    for (int rnd = 0; rnd < 2; rnd++) {
        const int dyi = rnd * NSLICE + slice;   // 0..7
        const bool active = (dyi < 7);
        const int dy = dyi - 3;

        if (rnd) BARS(bar);   // own slice's consume reads done before reuse

        if (active) {
            // produce 7 correlation maps C_{dy,dx} for this slice
            #pragma unroll
            for (int dxi = 0; dxi < 7; dxi++) {
                const int off = dy * PW + (dxi - 3);
                {
                    float4 wa = phiA[cell0 + off], wb = phiB[cell0 + off];
                    float cv = v0a.x*wa.x;
                    cv = fmaf(v0a.y, wa.y, cv); cv = fmaf(v0a.z, wa.z, cv);
                    cv = fmaf(v0a.w, wa.w, cv); cv = fmaf(v0b.x, wb.x, cv);
                    cv = fmaf(v0b.y, wb.y, cv); cv = fmaf(v0b.z, wb.z, cv);
                    cv = fmaf(v0b.w, wb.w, cv);
                    Cs[slice][dxi][p0] = cv;
                }
                if (has1) {
                    float4 wa = phiA[cell1 + off], wb = phiB[cell1 + off];
                    float cv = v1a.x*wa.x;
                    cv = fmaf(v1a.y, wa.y, cv); cv = fmaf(v1a.z, wa.z, cv);
                    cv = fmaf(v1a.w, wa.w, cv); cv = fmaf(v1b.x, wb.x, cv);
                    cv = fmaf(v1b.y, wb.y, cv); cv = fmaf(v1b.z, wb.z, cv);
                    cv = fmaf(v1b.w, wb.w, cv);
                    Cs[slice][dxi][p1] = cv;
                }
            }
        }
        BARS(bar);            // produce -> consume, slice-local

        if (active) {
            const bool in_y = ((unsigned)(gy + dy) < IMG_H);
            float l[7];
            #pragma unroll
            for (int dxi = 0; dxi < 7; dxi++) {
                const float* base = &Cs[slice][dxi][ty * CW + tx];
                float v = base[0]      + base[1]      + base[2]
                        + base[CW]     + base[CW+1]   + base[CW+2]
                        + base[2*CW]   + base[2*CW+1] + base[2*CW+2];
                const bool in = in_y && ((unsigned)(gx + dxi - 3) < IMG_W);
                l[dxi] = in ? v : 0.f;
            }
            float mrow = fmaxf(fmaxf(fmaxf(l[0], l[1]), fmaxf(l[2], l[3])),
                               fmaxf(fmaxf(l[4], l[5]), l[6]));
            float mn = fmaxf(m, mrow);
            float sc = __expf(m - mn);
            ssum *= sc;
            o0x *= sc; o0y *= sc; o0z *= sc; o0w *= sc;
            o1x *= sc; o1y *= sc; o1z *= sc; o1w *= sc;

            const int girow = (ty + HG + dy) * GW + tx;   // dxi adds 0..6
            #pragma unroll
            for (int dxi = 0; dxi < 7; dxi++) {
                float e = __expf(l[dxi] - mn);
                float4 gv0 = gA[girow + dxi];
                float4 gv1 = gB[girow + dxi];
                ssum += e;
                o0x = fmaf(e, gv0.x, o0x);  o0y = fmaf(e, gv0.y, o0y);
                o0z = fmaf(e, gv0.z, o0z);  o0w = fmaf(e, gv0.w, o0w);
                o1x = fmaf(e, gv1.x, o1x);  o1y = fmaf(e, gv1.y, o1y);
                o1z = fmaf(e, gv1.z, o1z);  o1w = fmaf(e, gv1.w, o1w);
            }
            m = mn;
        }
    }

    // ---- merge 4 per-slice partial softmaxes (reuse Cs as scratch) ----
    __syncthreads();                      // all slices done reading Cs
    float* red = &Cs[0][0][0];            // 4*7*184 = 5152 >= 10*512 floats
    red[tid]            = m;
    red[NTHREADS + tid] = ssum;
    red[2*NTHREADS + 0*NTHREADS + tid] = o0x;
    red[2*NTHREADS + 1*NTHREADS + tid] = o0y;
    red[2*NTHREADS + 2*NTHREADS + tid] = o0z;
    red[2*NTHREADS + 3*NTHREADS + tid] = o0w;
    red[2*NTHREADS + 4*NTHREADS + tid] = o1x;
    red[2*NTHREADS + 5*NTHREADS + tid] = o1y;
    red[2*NTHREADS + 6*NTHREADS + tid] = o1z;
    red[2*NTHREADS + 7*NTHREADS + tid] = o1w;
    __syncthreads();

    if (slice == 0) {
        float mm[NSLICE];
        #pragma unroll
        for (int s = 0; s < NSLICE; s++) mm[s] = red[s*NPIX + px];
        float M = fmaxf(fmaxf(mm[0], mm[1]), fmaxf(mm[2], mm[3]));

        float S = 0.f;
        float oo[NCH];
        #pragma unroll
        for (int ch = 0; ch < NCH; ch++) oo[ch] = 0.f;
        #pragma unroll
        for (int s = 0; s < NSLICE; s++) {
            float w = __expf(mm[s] - M);
            S = fmaf(red[NTHREADS + s*NPIX + px], w, S);
            #pragma unroll
            for (int ch = 0; ch < NCH; ch++)
                oo[ch] = fmaf(red[2*NTHREADS + ch*NTHREADS + s*NPIX + px], w, oo[ch]);
        }
        float inv = 1.f / S;
        float* ob = out + (size_t)bimg*NCH*PL + (size_t)gy*IMG_W + gx;
        #pragma unroll
        for (int ch = 0; ch < NCH; ch++)
            ob[ch*PL] = oo[ch] * inv;
    }
}

extern "C" void kernel_launch(void* const* d_in, const int* in_sizes, int n_in,
                              void* d_out, int out_size)
{
    const float* u    = (const float*)d_in[0];
    const float* pan  = (const float*)d_in[1];
    const float* Wphi = (const float*)d_in[2];
    const float* Wg   = (const float*)d_in[3];
    float* out = (float*)d_out;

    dim3 grid(IMG_W / TX, IMG_H / TY, NB);   // (8, 16, 2) = 256 blocks
    dim3 block(NTHREADS);                     // 512
    attn_slice_nb_kernel<<<grid, block>>>(u, pan, Wphi, Wg, out);
}

// round 6
// speedup vs baseline: 1.0252x; 1.0252x over previous
#include <cuda_runtime.h>
#include <cuda_bf16.h>

// Problem constants (fixed by the dataset: b=2, c=8, h=w=128, P=3, Wn=7)
#define IMG_H 128
#define IMG_W 128
#define NCH 8
#define NB 2
#define PL (IMG_H*IMG_W)

#define TY 8
#define TX 16
#define NPIX (TY*TX)           // 128 pixels per tile
#define NSLICE 4
#define NTHREADS (NPIX*NSLICE) // 512
#define HP 4                   // phi halo: window +-3 plus patch +-1
#define HG 3                   // g halo: window +-3
#define PH (TY + 2*HP)         // 16
#define PW (TX + 2*HP)         // 24
#define GH (TY + 2*HG)         // 14
#define GW (TX + 2*HG)         // 22
#define NPHI (PH*PW)           // 384
#define NG (GH*GW)             // 308

// Correlation map: tile dilated by 1 pixel (patch radius)
#define CW 18                  // TX + 2
#define CHh 10                 // TY + 2
#define CN (CHh*CW)            // 180 logical positions
#define CNP 184                // padded stride; Cs also doubles as merge scratch

// per-slice named barrier (4 consecutive warps = 128 threads)
#define BARS(id) asm volatile("bar.sync %0, %1;" :: "r"(id), "r"(128) : "memory")

// FMA-pipe exp: exp(x) for x <= 0 (post max-subtraction). Avoids the MUFU pipe
// (rt 8/SMSP, 0.5 op/cyc/SM) which was the binding roofline at ~15k ops/SM.
// 2^y split: n = round(y), f = y-n in [-0.5,0.5]; degree-4 poly (~4e-5 rel).
__device__ __forceinline__ float fexp(float x)
{
    float y = fmaxf(x, -80.f) * 1.44269504f;     // log2(e); clamp keeps n >= -116
    float r = y + 12582912.f;                    // 1.5*2^23: round-to-nearest int
    int   n = __float_as_int(r) - 0x4B400000;    // integer part of y
    float f = y - (r - 12582912.f);              // fraction in [-0.5, 0.5]
    float p =              0.00961813f;
    p = __fmaf_rn(p, f,    0.05550411f);
    p = __fmaf_rn(p, f,    0.24022651f);
    p = __fmaf_rn(p, f,    0.69314718f);
    p = __fmaf_rn(p, f,    1.0f);
    return __int_as_float(__float_as_int(p) + (n << 23));
}

__global__ __launch_bounds__(NTHREADS, 2)
void attn_slice_pexp_kernel(const float* __restrict__ u,
                            const float* __restrict__ pan,
                            const float* __restrict__ Wphi,
                            const float* __restrict__ Wg,
                            float* __restrict__ out)
{
    // channel-plane layout: conflict-free 16B-stride LDS.128
    __shared__ __align__(16) float4 phiA[NPHI], phiB[NPHI];
    __shared__ __align__(16) float4 gA[NG],  gB[NG];
    __shared__ float Cs[NSLICE][7][CNP];        // per-slice row of 7 corr maps
    __shared__ float wphi_s[NCH*NCH];
    __shared__ float wg_s[NCH*NCH];

    const int tid  = threadIdx.x;
    const int bimg = blockIdx.z;
    const int y0   = blockIdx.y * TY;
    const int x0   = blockIdx.x * TX;

    if (tid < NCH*NCH)              wphi_s[tid] = Wphi[tid];
    else if (tid < 2*NCH*NCH)       wg_s[tid - NCH*NCH] = Wg[tid - NCH*NCH];
    __syncthreads();

    const float* panb = pan + (size_t)bimg * NCH * PL;
    const float* ub   = u   + (size_t)bimg * NCH * PL;

    // ---- fused prologue: 692 units (384 phi cells + 308 g cells) over 512 thr ----
    #pragma unroll
    for (int base = 0; base < NPHI + NG; base += NTHREADS) {
        const int i = base + tid;
        if (i < NPHI) {
            // phi0 = W_phi @ pan with +-4 halo (zero outside image)
            int r = i / PW, c = i % PW;
            int yy = y0 - HP + r, xx = x0 - HP + c;
            bool in = ((unsigned)yy < IMG_H) && ((unsigned)xx < IMG_W);
            float pv[NCH];
            #pragma unroll
            for (int ch = 0; ch < NCH; ch++)
                pv[ch] = in ? panb[ch*PL + yy*IMG_W + xx] : 0.f;
            float po[NCH];
            #pragma unroll
            for (int o = 0; o < NCH; o++) {
                float acc = 0.f;
                #pragma unroll
                for (int ci = 0; ci < NCH; ci++)
                    acc = fmaf(wphi_s[o*NCH+ci], pv[ci], acc);
                po[o] = acc;
            }
            phiA[i] = make_float4(po[0], po[1], po[2], po[3]);
            phiB[i] = make_float4(po[4], po[5], po[6], po[7]);
        } else if (i < NPHI + NG) {
            // g = W_g @ u with +-3 halo (zero outside image)
            int j = i - NPHI;
            int r = j / GW, c = j % GW;
            int yy = y0 - HG + r, xx = x0 - HG + c;
            bool in = ((unsigned)yy < IMG_H) && ((unsigned)xx < IMG_W);
            float uv[NCH];
            #pragma unroll
            for (int ch = 0; ch < NCH; ch++)
                uv[ch] = in ? ub[ch*PL + yy*IMG_W + xx] : 0.f;
            float go[NCH];
            #pragma unroll
            for (int o = 0; o < NCH; o++) {
                float acc = 0.f;
                #pragma unroll
                for (int ci = 0; ci < NCH; ci++)
                    acc = fmaf(wg_s[o*NCH+ci], uv[ci], acc);
                go[o] = acc;
            }
            gA[j] = make_float4(go[0], go[1], go[2], go[3]);
            gB[j] = make_float4(go[4], go[5], go[6], go[7]);
        }
    }
    __syncthreads();

    const int px    = tid & (NPIX-1);      // pixel within tile
    const int slice = tid >> 7;            // 0..3
    const int bar   = slice + 1;           // named barrier id for this slice
    const int ty = px / TX, tx = px % TX;
    const int gy = y0 + ty, gx = x0 + tx;

    // correlation positions handled by this thread (within its slice)
    const int p0    = px;                            // 0..127
    const int cell0 = (p0/CW + 3) * PW + (p0%CW + 3);
    const float4 v0a = phiA[cell0];
    const float4 v0b = phiB[cell0];
    const bool has1 = (px < CN - NPIX);              // px < 52
    const int p1    = px + NPIX;
    const int cell1 = (p1/CW + 3) * PW + (p1%CW + 3);
    float4 v1a = make_float4(0,0,0,0), v1b = make_float4(0,0,0,0);
    if (has1) { v1a = phiA[cell1]; v1b = phiB[cell1]; }

    // partial online softmax over this slice's dy rows
    float m = -3.4e38f, ssum = 0.f;
    float o0x=0.f,o0y=0.f,o0z=0.f,o0w=0.f;
    float o1x=0.f,o1y=0.f,o1z=0.f,o1w=0.f;

    #pragma unroll
    for (int rnd = 0; rnd < 2; rnd++) {
        const int dyi = rnd * NSLICE + slice;   // 0..7
        const bool active = (dyi < 7);
        const int dy = dyi - 3;

        if (rnd) BARS(bar);   // own slice's consume reads done before reuse

        if (active) {
            // produce 7 correlation maps C_{dy,dx} for this slice
            #pragma unroll
            for (int dxi = 0; dxi < 7; dxi++) {
                const int off = dy * PW + (dxi - 3);
                {
                    float4 wa = phiA[cell0 + off], wb = phiB[cell0 + off];
                    float cv = v0a.x*wa.x;
                    cv = fmaf(v0a.y, wa.y, cv); cv = fmaf(v0a.z, wa.z, cv);
                    cv = fmaf(v0a.w, wa.w, cv); cv = fmaf(v0b.x, wb.x, cv);
                    cv = fmaf(v0b.y, wb.y, cv); cv = fmaf(v0b.z, wb.z, cv);
                    cv = fmaf(v0b.w, wb.w, cv);
                    Cs[slice][dxi][p0] = cv;
                }
                if (has1) {
                    float4 wa = phiA[cell1 + off], wb = phiB[cell1 + off];
                    float cv = v1a.x*wa.x;
                    cv = fmaf(v1a.y, wa.y, cv); cv = fmaf(v1a.z, wa.z, cv);
                    cv = fmaf(v1a.w, wa.w, cv); cv = fmaf(v1b.x, wb.x, cv);
                    cv = fmaf(v1b.y, wb.y, cv); cv = fmaf(v1b.z, wb.z, cv);
                    cv = fmaf(v1b.w, wb.w, cv);
                    Cs[slice][dxi][p1] = cv;
                }
            }
        }
        BARS(bar);            // produce -> consume, slice-local

        if (active) {
            const bool in_y = ((unsigned)(gy + dy) < IMG_H);
            float l[7];
            #pragma unroll
            for (int dxi = 0; dxi < 7; dxi++) {
                const float* base = &Cs[slice][dxi][ty * CW + tx];
                float v = base[0]      + base[1]      + base[2]
                        + base[CW]     + base[CW+1]   + base[CW+2]
                        + base[2*CW]   + base[2*CW+1] + base[2*CW+2];
                const bool in = in_y && ((unsigned)(gx + dxi - 3) < IMG_W);
                l[dxi] = in ? v : 0.f;
            }
            float mrow = fmaxf(fmaxf(fmaxf(l[0], l[1]), fmaxf(l[2], l[3])),
                               fmaxf(fmaxf(l[4], l[5]), l[6]));
            float mn = fmaxf(m, mrow);
            float sc = fexp(m - mn);
            ssum *= sc;
            o0x *= sc; o0y *= sc; o0z *= sc; o0w *= sc;
            o1x *= sc; o1y *= sc; o1z *= sc; o1w *= sc;

            const int girow = (ty + HG + dy) * GW + tx;   // dxi adds 0..6
            #pragma unroll
            for (int dxi = 0; dxi < 7; dxi++) {
                float e = fexp(l[dxi] - mn);
                float4 gv0 = gA[girow + dxi];
                float4 gv1 = gB[girow + dxi];
                ssum += e;
                o0x = fmaf(e, gv0.x, o0x);  o0y = fmaf(e, gv0.y, o0y);
                o0z = fmaf(e, gv0.z, o0z);  o0w = fmaf(e, gv0.w, o0w);
                o1x = fmaf(e, gv1.x, o1x);  o1y = fmaf(e, gv1.y, o1y);
                o1z = fmaf(e, gv1.z, o1z);  o1w = fmaf(e, gv1.w, o1w);
            }
            m = mn;
        }
    }

    // ---- merge 4 per-slice partial softmaxes (reuse Cs as scratch) ----
    __syncthreads();                      // all slices done reading Cs
    float* red = &Cs[0][0][0];            // 4*7*184 = 5152 >= 10*512 floats
    red[tid]            = m;
    red[NTHREADS + tid] = ssum;
    red[2*NTHREADS + 0*NTHREADS + tid] = o0x;
    red[2*NTHREADS + 1*NTHREADS + tid] = o0y;
    red[2*NTHREADS + 2*NTHREADS + tid] = o0z;
    red[2*NTHREADS + 3*NTHREADS + tid] = o0w;
    red[2*NTHREADS + 4*NTHREADS + tid] = o1x;
    red[2*NTHREADS + 5*NTHREADS + tid] = o1y;
    red[2*NTHREADS + 6*NTHREADS + tid] = o1z;
    red[2*NTHREADS + 7*NTHREADS + tid] = o1w;
    __syncthreads();

    if (slice == 0) {
        float mm[NSLICE];
        #pragma unroll
        for (int s = 0; s < NSLICE; s++) mm[s] = red[s*NPIX + px];
        float M = fmaxf(fmaxf(mm[0], mm[1]), fmaxf(mm[2], mm[3]));

        float S = 0.f;
        float oo[NCH];
        #pragma unroll
        for (int ch = 0; ch < NCH; ch++) oo[ch] = 0.f;
        #pragma unroll
        for (int s = 0; s < NSLICE; s++) {
            float w = fexp(mm[s] - M);
            S = fmaf(red[NTHREADS + s*NPIX + px], w, S);
            #pragma unroll
            for (int ch = 0; ch < NCH; ch++)
                oo[ch] = fmaf(red[2*NTHREADS + ch*NTHREADS + s*NPIX + px], w, oo[ch]);
        }
        float inv = 1.f / S;
        float* ob = out + (size_t)bimg*NCH*PL + (size_t)gy*IMG_W + gx;
        #pragma unroll
        for (int ch = 0; ch < NCH; ch++)
            ob[ch*PL] = oo[ch] * inv;
    }
}

extern "C" void kernel_launch(void* const* d_in, const int* in_sizes, int n_in,
                              void* d_out, int out_size)
{
    const float* u    = (const float*)d_in[0];
    const float* pan  = (const float*)d_in[1];
    const float* Wphi = (const float*)d_in[2];
    const float* Wg   = (const float*)d_in[3];
    float* out = (float*)d_out;

    dim3 grid(IMG_W / TX, IMG_H / TY, NB);   // (8, 16, 2) = 256 blocks
    dim3 block(NTHREADS);                     // 512
    attn_slice_pexp_kernel<<<grid, block>>>(u, pan, Wphi, Wg, out);
}

// round 7
// speedup vs baseline: 1.0292x; 1.0039x over previous
#include <cuda_runtime.h>
#include <cuda_bf16.h>

// Problem constants (fixed by the dataset: b=2, c=8, h=w=128, P=3, Wn=7)
#define IMG_H 128
#define IMG_W 128
#define NCH 8
#define NB 2
#define PL (IMG_H*IMG_W)

#define TY 8
#define TX 16
#define NPIX (TY*TX)           // 128 pixels per tile
#define NSLICE 4
#define NTHREADS (NPIX*NSLICE) // 512
#define HP 4                   // phi halo: window +-3 plus patch +-1
#define HG 3                   // g halo: window +-3
#define PH (TY + 2*HP)         // 16
#define PW (TX + 2*HP)         // 24
#define GH (TY + 2*HG)         // 14
#define GW (TX + 2*HG)         // 22
#define NPHI (PH*PW)           // 384
#define NG (GH*GW)             // 308

// Correlation map: tile dilated by 1 pixel (patch radius)
#define CW 18                  // TX + 2
#define CHh 10                 // TY + 2
#define CN (CHh*CW)            // 180 logical positions
#define CNP 184                // padded map stride (floats)
#define KMAX 13                // maps per slice (slice 0: 13, others: 12)

// ---- dynamic shared memory layout (bytes) ----
#define OFF_PHIA 0
#define OFF_PHIB (OFF_PHIA + NPHI*16)            // 6144
#define OFF_GA   (OFF_PHIB + NPHI*16)            // 12288
#define OFF_GB   (OFF_GA   + NG*16)              // 17216
#define OFF_CS   (OFF_GB   + NG*16)              // 22144
#define OFF_WPHI (OFF_CS   + NSLICE*KMAX*CNP*4)  // 60416
#define OFF_WG   (OFF_WPHI + 256)                // 60672
#define SMEM_TOTAL (OFF_WG + 256)                // 60928

// per-slice named barrier (4 consecutive warps = 128 threads)
#define BARS(id) asm volatile("bar.sync %0, %1;" :: "r"(id), "r"(128) : "memory")

// packed f32x2 ops (Blackwell): two fp32 lanes per instruction on the FMA pipe
#define MUL2(out, a, b) \
    asm("mul.rn.f32x2 %0, %1, %2;" : "=l"(out) : "l"(a), "l"(b))
#define FMA2(out, a, b, c) \
    asm("fma.rn.f32x2 %0, %1, %2, %3;" : "=l"(out) : "l"(a), "l"(b), "l"(c))
#define PACK2(out, lo, hi) \
    asm("mov.b64 %0, {%1, %2};" : "=l"(out) : "f"(lo), "f"(hi))
#define UNPACK2(lo, hi, in) \
    asm("mov.b64 {%0, %1}, %2;" : "=f"(lo), "=f"(hi) : "l"(in))

// FMA-pipe exp for x <= 0 (post max-subtraction); ~4e-5 rel err.
__device__ __forceinline__ float fexp(float x)
{
    float y = fmaxf(x, -80.f) * 1.44269504f;
    float r = y + 12582912.f;                    // 1.5*2^23 round-to-int
    int   n = __float_as_int(r) - 0x4B400000;
    float f = y - (r - 12582912.f);
    float p =              0.00961813f;
    p = __fmaf_rn(p, f,    0.05550411f);
    p = __fmaf_rn(p, f,    0.24022651f);
    p = __fmaf_rn(p, f,    0.69314718f);
    p = __fmaf_rn(p, f,    1.0f);
    return __int_as_float(__float_as_int(p) + (n << 23));
}

__global__ __launch_bounds__(NTHREADS, 2)
void attn_oneshot_kernel(const float* __restrict__ u,
                         const float* __restrict__ pan,
                         const float* __restrict__ Wphi,
                         const float* __restrict__ Wg,
                         float* __restrict__ out)
{
    extern __shared__ __align__(16) char smem_raw[];
    float4* phiA = (float4*)(smem_raw + OFF_PHIA);
    float4* phiB = (float4*)(smem_raw + OFF_PHIB);
    float4* gA   = (float4*)(smem_raw + OFF_GA);
    float4* gB   = (float4*)(smem_raw + OFF_GB);
    float*  Csb  = (float*)(smem_raw + OFF_CS);     // NSLICE*KMAX maps of CNP
    float*  wphi_s = (float*)(smem_raw + OFF_WPHI);
    float*  wg_s   = (float*)(smem_raw + OFF_WG);

    const int tid  = threadIdx.x;
    const int bimg = blockIdx.z;
    const int y0   = blockIdx.y * TY;
    const int x0   = blockIdx.x * TX;

    if (tid < NCH*NCH)              wphi_s[tid] = Wphi[tid];
    else if (tid < 2*NCH*NCH)       wg_s[tid - NCH*NCH] = Wg[tid - NCH*NCH];
    __syncthreads();

    const float* panb = pan + (size_t)bimg * NCH * PL;
    const float* ub   = u   + (size_t)bimg * NCH * PL;

    // ---- fused prologue: 692 units (384 phi + 308 g cells) over 512 threads ----
    #pragma unroll
    for (int base = 0; base < NPHI + NG; base += NTHREADS) {
        const int i = base + tid;
        if (i < NPHI) {
            int r = i / PW, c = i % PW;
            int yy = y0 - HP + r, xx = x0 - HP + c;
            bool in = ((unsigned)yy < IMG_H) && ((unsigned)xx < IMG_W);
            float pv[NCH];
            #pragma unroll
            for (int ch = 0; ch < NCH; ch++)
                pv[ch] = in ? panb[ch*PL + yy*IMG_W + xx] : 0.f;
            float po[NCH];
            #pragma unroll
            for (int o = 0; o < NCH; o++) {
                float acc = 0.f;
                #pragma unroll
                for (int ci = 0; ci < NCH; ci++)
                    acc = fmaf(wphi_s[o*NCH+ci], pv[ci], acc);
                po[o] = acc;
            }
            phiA[i] = make_float4(po[0], po[1], po[2], po[3]);
            phiB[i] = make_float4(po[4], po[5], po[6], po[7]);
        } else if (i < NPHI + NG) {
            int j = i - NPHI;
            int r = j / GW, c = j % GW;
            int yy = y0 - HG + r, xx = x0 - HG + c;
            bool in = ((unsigned)yy < IMG_H) && ((unsigned)xx < IMG_W);
            float uv[NCH];
            #pragma unroll
            for (int ch = 0; ch < NCH; ch++)
                uv[ch] = in ? ub[ch*PL + yy*IMG_W + xx] : 0.f;
            float go[NCH];
            #pragma unroll
            for (int o = 0; o < NCH; o++) {
                float acc = 0.f;
                #pragma unroll
                for (int ci = 0; ci < NCH; ci++)
                    acc = fmaf(wg_s[o*NCH+ci], uv[ci], acc);
                go[o] = acc;
            }
            gA[j] = make_float4(go[0], go[1], go[2], go[3]);
            gB[j] = make_float4(go[4], go[5], go[6], go[7]);
        }
    }
    __syncthreads();

    const int px    = tid & (NPIX-1);
    const int slice = tid >> 7;            // 0..3, owns offsets j = slice + 4k
    const int bar   = slice + 1;
    const int ty = px / TX, tx = px % TX;
    const int gy = y0 + ty, gx = x0 + tx;

    // correlation positions handled by this thread (within its slice)
    const int p0    = px;
    const int cell0 = (p0/CW + 3) * PW + (p0%CW + 3);
    const bool has1 = (px < CN - NPIX);              // px < 52
    const int p1    = px + NPIX;
    const int cell1 = has1 ? (p1/CW + 3) * PW + (p1%CW + 3) : cell0;

    // cache v(a) as packed f32x2
    unsigned long long v0p0, v0p1, v0p2, v0p3, v1p0, v1p1, v1p2, v1p3;
    {
        ulonglong2 a = *(const ulonglong2*)&phiA[cell0];
        ulonglong2 b = *(const ulonglong2*)&phiB[cell0];
        v0p0 = a.x; v0p1 = a.y; v0p2 = b.x; v0p3 = b.y;
        ulonglong2 a1 = *(const ulonglong2*)&phiA[cell1];
        ulonglong2 b1 = *(const ulonglong2*)&phiB[cell1];
        v1p0 = a1.x; v1p1 = a1.y; v1p2 = b1.x; v1p3 = b1.y;
    }

    float* Cme = Csb + slice * (KMAX*CNP);

    // ---- produce all maps for this slice (12-13 independent dot chains) ----
    #pragma unroll
    for (int k = 0; k < KMAX; k++) {
        const int j = slice + 4*k;
        if (j < 49) {
            const int dy = ((j * 9363) >> 16) - 3;       // j/7 - 3
            const int dx = (j - (dy+3)*7) - 3;
            const int off = dy * PW + dx;
            {
                ulonglong2 wa = *(const ulonglong2*)&phiA[cell0 + off];
                ulonglong2 wb = *(const ulonglong2*)&phiB[cell0 + off];
                unsigned long long acc;
                MUL2(acc, v0p0, wa.x);
                FMA2(acc, v0p1, wa.y, acc);
                FMA2(acc, v0p2, wb.x, acc);
                FMA2(acc, v0p3, wb.y, acc);
                float lo, hi; UNPACK2(lo, hi, acc);
                Cme[k*CNP + p0] = lo + hi;
            }
            if (has1) {
                ulonglong2 wa = *(const ulonglong2*)&phiA[cell1 + off];
                ulonglong2 wb = *(const ulonglong2*)&phiB[cell1 + off];
                unsigned long long acc;
                MUL2(acc, v1p0, wa.x);
                FMA2(acc, v1p1, wa.y, acc);
                FMA2(acc, v1p2, wb.x, acc);
                FMA2(acc, v1p3, wb.y, acc);
                float lo, hi; UNPACK2(lo, hi, acc);
                Cme[k*CNP + p1] = lo + hi;
            }
        }
    }
    BARS(bar);     // slice-local produce -> consume

    // ---- pass 1: all logits of this slice via 3x3 box-sums, track max ----
    float l[KMAX];
    float M = -3.4e38f;
    #pragma unroll
    for (int k = 0; k < KMAX; k++) {
        const int j = slice + 4*k;
        if (j < 49) {
            const int dy = ((j * 9363) >> 16) - 3;
            const int dx = (j - (dy+3)*7) - 3;
            const float* base = &Cme[k*CNP + ty*CW + tx];
            float v = base[0]      + base[1]      + base[2]
                    + base[CW]     + base[CW+1]   + base[CW+2]
                    + base[2*CW]   + base[2*CW+1] + base[2*CW+2];
            const bool in = ((unsigned)(gy+dy) < IMG_H) && ((unsigned)(gx+dx) < IMG_W);
            l[k] = in ? v : 0.f;          // double-unfold: OOB logit exactly 0
            M = fmaxf(M, l[k]);
        } else {
            l[k] = -1e30f;                // exp -> ~0
        }
    }

    // ---- pass 2: exp + packed accumulation of g ----
    float S = 0.f;
    unsigned long long o01 = 0ULL, o23 = 0ULL, o45 = 0ULL, o67 = 0ULL;
    #pragma unroll
    for (int k = 0; k < KMAX; k++) {
        const int j = slice + 4*k;
        if (j < 49) {
            const int dy = ((j * 9363) >> 16) - 3;
            const int dx = (j - (dy+3)*7) - 3;
            float e = fexp(l[k] - M);
            S += e;
            unsigned long long e2; PACK2(e2, e, e);
            const int gi = (ty + HG + dy) * GW + (tx + HG + dx);
            ulonglong2 g0 = *(const ulonglong2*)&gA[gi];
            ulonglong2 g1 = *(const ulonglong2*)&gB[gi];
            FMA2(o01, e2, g0.x, o01);
            FMA2(o23, e2, g0.y, o23);
            FMA2(o45, e2, g1.x, o45);
            FMA2(o67, e2, g1.y, o67);
        }
    }

    // ---- merge 4 per-slice partials (reuse Cs region as scratch) ----
    __syncthreads();                      // all slices done with Cs
    float o0,o1,o2,o3,o4,o5,o6,o7;
    UNPACK2(o0,o1,o01); UNPACK2(o2,o3,o23);
    UNPACK2(o4,o5,o45); UNPACK2(o6,o7,o67);
    float* red = Csb;                     // 4*13*184 = 9568 >= 10*512 floats
    red[tid]            = M;
    red[NTHREADS + tid] = S;
    red[2*NTHREADS + 0*NTHREADS + tid] = o0;
    red[2*NTHREADS + 1*NTHREADS + tid] = o1;
    red[2*NTHREADS + 2*NTHREADS + tid] = o2;
    red[2*NTHREADS + 3*NTHREADS + tid] = o3;
    red[2*NTHREADS + 4*NTHREADS + tid] = o4;
    red[2*NTHREADS + 5*NTHREADS + tid] = o5;
    red[2*NTHREADS + 6*NTHREADS + tid] = o6;
    red[2*NTHREADS + 7*NTHREADS + tid] = o7;
    __syncthreads();

    if (slice == 0) {
        float mm[NSLICE];
        #pragma unroll
        for (int s = 0; s < NSLICE; s++) mm[s] = red[s*NPIX + px];
        float Mt = fmaxf(fmaxf(mm[0], mm[1]), fmaxf(mm[2], mm[3]));

        float St = 0.f;
        float oo[NCH];
        #pragma unroll
        for (int ch = 0; ch < NCH; ch++) oo[ch] = 0.f;
        #pragma unroll
        for (int s = 0; s < NSLICE; s++) {
            float w = fexp(mm[s] - Mt);
            St = fmaf(red[NTHREADS + s*NPIX + px], w, St);
            #pragma unroll
            for (int ch = 0; ch < NCH; ch++)
                oo[ch] = fmaf(red[2*NTHREADS + ch*NTHREADS + s*NPIX + px], w, oo[ch]);
        }
        float inv = 1.f / St;
        float* ob = out + (size_t)bimg*NCH*PL + (size_t)gy*IMG_W + gx;
        #pragma unroll
        for (int ch = 0; ch < NCH; ch++)
            ob[ch*PL] = oo[ch] * inv;
    }
}

extern "C" void kernel_launch(void* const* d_in, const int* in_sizes, int n_in,
                              void* d_out, int out_size)
{
    const float* u    = (const float*)d_in[0];
    const float* pan  = (const float*)d_in[1];
    const float* Wphi = (const float*)d_in[2];
    const float* Wg   = (const float*)d_in[3];
    float* out = (float*)d_out;

    cudaFuncSetAttribute(attn_oneshot_kernel,
                         cudaFuncAttributeMaxDynamicSharedMemorySize, SMEM_TOTAL);

    dim3 grid(IMG_W / TX, IMG_H / TY, NB);   // (8, 16, 2) = 256 blocks
    dim3 block(NTHREADS);                     // 512
    attn_oneshot_kernel<<<grid, block, SMEM_TOTAL>>>(u, pan, Wphi, Wg, out);
}

// round 8
// speedup vs baseline: 1.0313x; 1.0020x over previous
#include <cuda_runtime.h>
#include <cuda_bf16.h>

// Problem constants (fixed by the dataset: b=2, c=8, h=w=128, P=3, Wn=7)
#define IMG_H 128
#define IMG_W 128
#define NCH 8
#define NB 2
#define PL (IMG_H*IMG_W)

#define TY 8
#define TX 16
#define NPIX (TY*TX)           // 128 pixels per tile
#define NSLICE 4
#define NTHREADS (NPIX*NSLICE) // 512
#define HP 4                   // phi halo: window +-3 plus patch +-1
#define HG 3                   // g halo: window +-3
#define PH (TY + 2*HP)         // 16
#define PW (TX + 2*HP)         // 24
#define GH (TY + 2*HG)         // 14
#define GW (TX + 2*HG)         // 22
#define NPHI (PH*PW)           // 384
#define NG (GH*GW)             // 308

// Correlation map: tile dilated by 1 pixel (patch radius)
#define CW 18                  // TX + 2
#define CHh 10                 // TY + 2
#define CN (CHh*CW)            // 180 logical positions
#define CNP 184                // padded map stride (floats)
#define KMAX 13                // maps per slice (slice 0: 13, others: 12)

// H map: horizontal 3-sums, 10 rows x 16 cols per correlation map
#define HW 16
#define HN (CHh*HW)            // 160
#define HPAIRS (CHh*HW/2)      // 80 pair-units per map
#define HUNITS (KMAX*HPAIRS)   // 1040 pair-units per slice

// ---- dynamic shared memory layout (bytes) ----
#define OFF_PHIA 0
#define OFF_PHIB (OFF_PHIA + NPHI*16)            // 6144
#define OFF_GA   (OFF_PHIB + NPHI*16)            // 12288
#define OFF_GB   (OFF_GA   + NG*16)              // 17216
#define OFF_CS   (OFF_GB   + NG*16)              // 22144
#define OFF_WPHI (OFF_CS   + NSLICE*KMAX*CNP*4)  // 60416
#define OFF_WG   (OFF_WPHI + 256)                // 60672
#define OFF_HS   (OFF_WG   + 256)                // 60928
#define SMEM_TOTAL (OFF_HS + NSLICE*KMAX*HN*4)   // 94208

// per-slice named barrier (4 consecutive warps = 128 threads)
#define BARS(id) asm volatile("bar.sync %0, %1;" :: "r"(id), "r"(128) : "memory")

// packed f32x2 ops (Blackwell): two fp32 lanes per instruction on the FMA pipe
#define MUL2(out, a, b) \
    asm("mul.rn.f32x2 %0, %1, %2;" : "=l"(out) : "l"(a), "l"(b))
#define FMA2(out, a, b, c) \
    asm("fma.rn.f32x2 %0, %1, %2, %3;" : "=l"(out) : "l"(a), "l"(b), "l"(c))
#define PACK2(out, lo, hi) \
    asm("mov.b64 %0, {%1, %2};" : "=l"(out) : "f"(lo), "f"(hi))
#define UNPACK2(lo, hi, in) \
    asm("mov.b64 {%0, %1}, %2;" : "=f"(lo), "=f"(hi) : "l"(in))

// FMA-pipe exp for x <= 0 (post max-subtraction); ~4e-5 rel err.
__device__ __forceinline__ float fexp(float x)
{
    float y = fmaxf(x, -80.f) * 1.44269504f;
    float r = y + 12582912.f;                    // 1.5*2^23 round-to-int
    int   n = __float_as_int(r) - 0x4B400000;
    float f = y - (r - 12582912.f);
    float p =              0.00961813f;
    p = __fmaf_rn(p, f,    0.05550411f);
    p = __fmaf_rn(p, f,    0.24022651f);
    p = __fmaf_rn(p, f,    0.69314718f);
    p = __fmaf_rn(p, f,    1.0f);
    return __int_as_float(__float_as_int(p) + (n << 23));
}

__global__ __launch_bounds__(NTHREADS, 2)
void attn_sep_kernel(const float* __restrict__ u,
                     const float* __restrict__ pan,
                     const float* __restrict__ Wphi,
                     const float* __restrict__ Wg,
                     float* __restrict__ out)
{
    extern __shared__ __align__(16) char smem_raw[];
    float4* phiA = (float4*)(smem_raw + OFF_PHIA);
    float4* phiB = (float4*)(smem_raw + OFF_PHIB);
    float4* gA   = (float4*)(smem_raw + OFF_GA);
    float4* gB   = (float4*)(smem_raw + OFF_GB);
    float*  Csb  = (float*)(smem_raw + OFF_CS);
    float*  wphi_s = (float*)(smem_raw + OFF_WPHI);
    float*  wg_s   = (float*)(smem_raw + OFF_WG);
    float*  Hsb  = (float*)(smem_raw + OFF_HS);

    const int tid  = threadIdx.x;
    const int bimg = blockIdx.z;
    const int y0   = blockIdx.y * TY;
    const int x0   = blockIdx.x * TX;

    if (tid < NCH*NCH)              wphi_s[tid] = Wphi[tid];
    else if (tid < 2*NCH*NCH)       wg_s[tid - NCH*NCH] = Wg[tid - NCH*NCH];
    __syncthreads();

    const float* panb = pan + (size_t)bimg * NCH * PL;
    const float* ub   = u   + (size_t)bimg * NCH * PL;

    // ---- fused prologue: 692 units (384 phi + 308 g cells) over 512 threads ----
    #pragma unroll
    for (int base = 0; base < NPHI + NG; base += NTHREADS) {
        const int i = base + tid;
        if (i < NPHI) {
            int r = i / PW, c = i % PW;
            int yy = y0 - HP + r, xx = x0 - HP + c;
            bool in = ((unsigned)yy < IMG_H) && ((unsigned)xx < IMG_W);
            float pv[NCH];
            #pragma unroll
            for (int ch = 0; ch < NCH; ch++)
                pv[ch] = in ? panb[ch*PL + yy*IMG_W + xx] : 0.f;
            float po[NCH];
            #pragma unroll
            for (int o = 0; o < NCH; o++) {
                float acc = 0.f;
                #pragma unroll
                for (int ci = 0; ci < NCH; ci++)
                    acc = fmaf(wphi_s[o*NCH+ci], pv[ci], acc);
                po[o] = acc;
            }
            phiA[i] = make_float4(po[0], po[1], po[2], po[3]);
            phiB[i] = make_float4(po[4], po[5], po[6], po[7]);
        } else if (i < NPHI + NG) {
            int j = i - NPHI;
            int r = j / GW, c = j % GW;
            int yy = y0 - HG + r, xx = x0 - HG + c;
            bool in = ((unsigned)yy < IMG_H) && ((unsigned)xx < IMG_W);
            float uv[NCH];
            #pragma unroll
            for (int ch = 0; ch < NCH; ch++)
                uv[ch] = in ? ub[ch*PL + yy*IMG_W + xx] : 0.f;
            float go[NCH];
            #pragma unroll
            for (int o = 0; o < NCH; o++) {
                float acc = 0.f;
                #pragma unroll
                for (int ci = 0; ci < NCH; ci++)
                    acc = fmaf(wg_s[o*NCH+ci], uv[ci], acc);
                go[o] = acc;
            }
            gA[j] = make_float4(go[0], go[1], go[2], go[3]);
            gB[j] = make_float4(go[4], go[5], go[6], go[7]);
        }
    }
    __syncthreads();

    const int px    = tid & (NPIX-1);
    const int slice = tid >> 7;            // 0..3, owns offsets j = slice + 4k
    const int bar   = slice + 1;
    const int ty = px / TX, tx = px % TX;
    const int gy = y0 + ty, gx = x0 + tx;

    // correlation positions handled by this thread (within its slice)
    const int p0    = px;
    const int cell0 = (p0/CW + 3) * PW + (p0%CW + 3);
    const bool has1 = (px < CN - NPIX);              // px < 52
    const int p1    = px + NPIX;
    const int cell1 = has1 ? (p1/CW + 3) * PW + (p1%CW + 3) : cell0;

    // cache v(a) as packed f32x2
    unsigned long long v0p0, v0p1, v0p2, v0p3, v1p0, v1p1, v1p2, v1p3;
    {
        ulonglong2 a = *(const ulonglong2*)&phiA[cell0];
        ulonglong2 b = *(const ulonglong2*)&phiB[cell0];
        v0p0 = a.x; v0p1 = a.y; v0p2 = b.x; v0p3 = b.y;
        ulonglong2 a1 = *(const ulonglong2*)&phiA[cell1];
        ulonglong2 b1 = *(const ulonglong2*)&phiB[cell1];
        v1p0 = a1.x; v1p1 = a1.y; v1p2 = b1.x; v1p3 = b1.y;
    }

    float* Cme = Csb + slice * (KMAX*CNP);
    float* Hme = Hsb + slice * (KMAX*HN);

    // ---- produce all C maps for this slice (12-13 independent dot chains) ----
    #pragma unroll
    for (int k = 0; k < KMAX; k++) {
        const int j = slice + 4*k;
        if (j < 49) {
            const int dy = ((j * 9363) >> 16) - 3;       // j/7 - 3
            const int dx = (j - (dy+3)*7) - 3;
            const int off = dy * PW + dx;
            {
                ulonglong2 wa = *(const ulonglong2*)&phiA[cell0 + off];
                ulonglong2 wb = *(const ulonglong2*)&phiB[cell0 + off];
                unsigned long long acc;
                MUL2(acc, v0p0, wa.x);
                FMA2(acc, v0p1, wa.y, acc);
                FMA2(acc, v0p2, wb.x, acc);
                FMA2(acc, v0p3, wb.y, acc);
                float lo, hi; UNPACK2(lo, hi, acc);
                Cme[k*CNP + p0] = lo + hi;
            }
            if (has1) {
                ulonglong2 wa = *(const ulonglong2*)&phiA[cell1 + off];
                ulonglong2 wb = *(const ulonglong2*)&phiB[cell1 + off];
                unsigned long long acc;
                MUL2(acc, v1p0, wa.x);
                FMA2(acc, v1p1, wa.y, acc);
                FMA2(acc, v1p2, wb.x, acc);
                FMA2(acc, v1p3, wb.y, acc);
                float lo, hi; UNPACK2(lo, hi, acc);
                Cme[k*CNP + p1] = lo + hi;
            }
        }
    }
    BARS(bar);     // slice-local: C produce -> H stage

    // ---- H stage: H(k,r,c) = C[r][c]+C[r][c+1]+C[r][c+2], pairs of columns ----
    // 1040 pair-units per slice over 128 threads (8-9 each)
    #pragma unroll
    for (int i = 0; i < 9; i++) {
        const int uu = px + 128*i;
        if (uu < HUNITS) {
            const int k  = uu / HPAIRS;          // map index (compiler magic div)
            const int pr = uu - k*HPAIRS;        // 0..79
            const int r  = pr >> 3;              // row 0..9
            const int c0 = (pr & 7) << 1;        // even col 0..14
            const float2 a = *(const float2*)&Cme[k*CNP + r*CW + c0];
            const float2 b = *(const float2*)&Cme[k*CNP + r*CW + c0 + 2];
            float h0 = a.x + a.y + b.x;
            float h1 = a.y + b.x + b.y;
            *(float2*)&Hme[k*HN + r*HW + c0] = make_float2(h0, h1);
        }
    }
    BARS(bar);     // H stage -> logits

    // ---- pass 1: logits = vertical 3-sum of H; track max ----
    float l[KMAX];
    float M = -3.4e38f;
    #pragma unroll
    for (int k = 0; k < KMAX; k++) {
        const int j = slice + 4*k;
        if (j < 49) {
            const int dy = ((j * 9363) >> 16) - 3;
            const int dx = (j - (dy+3)*7) - 3;
            const float* hb = &Hme[k*HN + ty*HW + tx];
            float v = hb[0] + hb[HW] + hb[2*HW];
            const bool in = ((unsigned)(gy+dy) < IMG_H) && ((unsigned)(gx+dx) < IMG_W);
            l[k] = in ? v : 0.f;          // double-unfold: OOB logit exactly 0
            M = fmaxf(M, l[k]);
        } else {
            l[k] = -1e30f;                // exp -> ~0
        }
    }

    // ---- pass 2: exp + packed accumulation of g ----
    float S = 0.f;
    unsigned long long o01 = 0ULL, o23 = 0ULL, o45 = 0ULL, o67 = 0ULL;
    #pragma unroll
    for (int k = 0; k < KMAX; k++) {
        const int j = slice + 4*k;
        if (j < 49) {
            const int dy = ((j * 9363) >> 16) - 3;
            const int dx = (j - (dy+3)*7) - 3;
            float e = fexp(l[k] - M);
            S += e;
            unsigned long long e2; PACK2(e2, e, e);
            const int gi = (ty + HG + dy) * GW + (tx + HG + dx);
            ulonglong2 g0 = *(const ulonglong2*)&gA[gi];
            ulonglong2 g1 = *(const ulonglong2*)&gB[gi];
            FMA2(o01, e2, g0.x, o01);
            FMA2(o23, e2, g0.y, o23);
            FMA2(o45, e2, g1.x, o45);
            FMA2(o67, e2, g1.y, o67);
        }
    }

    // ---- merge 4 per-slice partials; ALL slices participate ----
    __syncthreads();                      // all slices done with Cs
    float o0,o1,o2,o3,o4,o5,o6,o7;
    UNPACK2(o0,o1,o01); UNPACK2(o2,o3,o23);
    UNPACK2(o4,o5,o45); UNPACK2(o6,o7,o67);
    float* red = Csb;                     // 10*512 = 5120 floats of scratch
    red[tid]            = M;
    red[NTHREADS + tid] = S;
    red[2*NTHREADS + 0*NTHREADS + tid] = o0;
    red[2*NTHREADS + 1*NTHREADS + tid] = o1;
    red[2*NTHREADS + 2*NTHREADS + tid] = o2;
    red[2*NTHREADS + 3*NTHREADS + tid] = o3;
    red[2*NTHREADS + 4*NTHREADS + tid] = o4;
    red[2*NTHREADS + 5*NTHREADS + tid] = o5;
    red[2*NTHREADS + 6*NTHREADS + tid] = o6;
    red[2*NTHREADS + 7*NTHREADS + tid] = o7;
    __syncthreads();

    {
        // every slice: recompute total max/sum (cheap), then write 2 channels
        float mm0 = red[0*NPIX + px], mm1 = red[1*NPIX + px];
        float mm2 = red[2*NPIX + px], mm3 = red[3*NPIX + px];
        float Mt = fmaxf(fmaxf(mm0, mm1), fmaxf(mm2, mm3));
        float w0 = fexp(mm0 - Mt), w1 = fexp(mm1 - Mt);
        float w2 = fexp(mm2 - Mt), w3 = fexp(mm3 - Mt);
        float St = w0*red[NTHREADS + 0*NPIX + px]
                 + w1*red[NTHREADS + 1*NPIX + px]
                 + w2*red[NTHREADS + 2*NPIX + px]
                 + w3*red[NTHREADS + 3*NPIX + px];
        float inv = 1.f / St;

        const int ch0 = 2*slice;
        float* ob = out + (size_t)bimg*NCH*PL + (size_t)gy*IMG_W + gx;
        #pragma unroll
        for (int cc = 0; cc < 2; cc++) {
            const int ch = ch0 + cc;
            const float* rc = red + 2*NTHREADS + ch*NTHREADS + px;
            float v = w0*rc[0*NPIX] + w1*rc[1*NPIX]
                    + w2*rc[2*NPIX] + w3*rc[3*NPIX];
            ob[ch*PL] = v * inv;
        }
    }
}

extern "C" void kernel_launch(void* const* d_in, const int* in_sizes, int n_in,
                              void* d_out, int out_size)
{
    const float* u    = (const float*)d_in[0];
    const float* pan  = (const float*)d_in[1];
    const float* Wphi = (const float*)d_in[2];
    const float* Wg   = (const float*)d_in[3];
    float* out = (float*)d_out;

    cudaFuncSetAttribute(attn_sep_kernel,
                         cudaFuncAttributeMaxDynamicSharedMemorySize, SMEM_TOTAL);

    dim3 grid(IMG_W / TX, IMG_H / TY, NB);   // (8, 16, 2) = 256 blocks
    dim3 block(NTHREADS);                     // 512
    attn_sep_kernel<<<grid, block, SMEM_TOTAL>>>(u, pan, Wphi, Wg, out);
}

// round 9
// speedup vs baseline: 1.1046x; 1.0711x over previous
#include <cuda_runtime.h>
#include <cuda_bf16.h>

// Problem constants (fixed by the dataset: b=2, c=8, h=w=128, P=3, Wn=7)
#define IMG_H 128
#define IMG_W 128
#define NCH 8
#define NB 2
#define PL (IMG_H*IMG_W)

#define TY 8
#define TX 16
#define NPIX (TY*TX)           // 128 pixels per tile
#define NSLICE 4
#define NTHREADS (NPIX*NSLICE) // 512
#define HP 4                   // phi halo
#define HG 3                   // g halo
#define PH (TY + 2*HP)         // 16
#define PW (TX + 2*HP)         // 24
#define GH (TY + 2*HG)         // 14
#define GW (TX + 2*HG)         // 22
#define NPHI (PH*PW)           // 384
#define NG (GH*GW)             // 308

#define CW 18
#define CHh 10
#define CN (CHh*CW)            // 180
#define CNP 184
#define KMAX 13                // maps per slice (slice 0: 13, others: 12)

#define HW 16
#define HN (CHh*HW)            // 160
#define HPAIRS (CHh*HW/2)      // 80
#define HUNITS (KMAX*HPAIRS)   // 1040

// ---- dynamic shared memory layout (bytes) ----
#define OFF_PHIA 0
#define OFF_PHIB (OFF_PHIA + NPHI*16)
#define OFF_GA   (OFF_PHIB + NPHI*16)
#define OFF_GB   (OFF_GA   + NG*16)
#define OFF_CS   (OFF_GB   + NG*16)
#define OFF_WPHI (OFF_CS   + NSLICE*KMAX*CNP*4)
#define OFF_WG   (OFF_WPHI + 256)
#define OFF_HS   (OFF_WG   + 256)
#define SMEM_TOTAL (OFF_HS + NSLICE*KMAX*HN*4)   // 94208

#define BARS(id) asm volatile("bar.sync %0, %1;" :: "r"(id), "r"(128) : "memory")

#define MUL2(out, a, b) \
    asm("mul.rn.f32x2 %0, %1, %2;" : "=l"(out) : "l"(a), "l"(b))
#define FMA2(out, a, b, c) \
    asm("fma.rn.f32x2 %0, %1, %2, %3;" : "=l"(out) : "l"(a), "l"(b), "l"(c))
#define PACK2(out, lo, hi) \
    asm("mov.b64 %0, {%1, %2};" : "=l"(out) : "f"(lo), "f"(hi))
#define UNPACK2(lo, hi, in) \
    asm("mov.b64 {%0, %1}, %2;" : "=f"(lo), "=f"(hi) : "l"(in))

// FMA-pipe exp, input clamped at -80 (only hits weights <= e^-50 of max term).
__device__ __forceinline__ float fexp(float x)
{
    float y = fmaxf(x, -80.f) * 1.44269504f;
    float r = y + 12582912.f;
    int   n = __float_as_int(r) - 0x4B400000;
    float f = y - (r - 12582912.f);
    float p =              0.00961813f;
    p = __fmaf_rn(p, f,    0.05550411f);
    p = __fmaf_rn(p, f,    0.24022651f);
    p = __fmaf_rn(p, f,    0.69314718f);
    p = __fmaf_rn(p, f,    1.0f);
    return __int_as_float(__float_as_int(p) + (n << 23));
}

__global__ __launch_bounds__(NTHREADS, 2)
void attn_shift_kernel(const float* __restrict__ u,
                       const float* __restrict__ pan,
                       const float* __restrict__ Wphi,
                       const float* __restrict__ Wg,
                       float* __restrict__ out)
{
    extern __shared__ __align__(16) char smem_raw[];
    float4* phiA = (float4*)(smem_raw + OFF_PHIA);
    float4* phiB = (float4*)(smem_raw + OFF_PHIB);
    float4* gA   = (float4*)(smem_raw + OFF_GA);
    float4* gB   = (float4*)(smem_raw + OFF_GB);
    float*  Csb  = (float*)(smem_raw + OFF_CS);
    float*  wphi_s = (float*)(smem_raw + OFF_WPHI);
    float*  wg_s   = (float*)(smem_raw + OFF_WG);
    float*  Hsb  = (float*)(smem_raw + OFF_HS);

    const int tid  = threadIdx.x;
    const int bimg = blockIdx.z;
    const int y0   = blockIdx.y * TY;
    const int x0   = blockIdx.x * TX;

    const float* panb = pan + (size_t)bimg * NCH * PL;
    const float* ub   = u   + (size_t)bimg * NCH * PL;

    // ---- prologue: issue input LDGs FIRST (in flight across the weight sync) ----
    // unit A: phi cell tid (tid<384); unit B: g cell (tid-384, or tid+128 if tid<180)
    const bool doPhi = (tid < NPHI);
    const int  gcell = (tid >= NPHI) ? (tid - NPHI)
                     : (tid < NG - NPIX ? tid + NPIX : -1);

    float pv[NCH], uv[NCH];
    int phi_i = 0;
    if (doPhi) {
        phi_i = tid;
        int r = tid / PW, c = tid % PW;
        int yy = y0 - HP + r, xx = x0 - HP + c;
        bool in = ((unsigned)yy < IMG_H) && ((unsigned)xx < IMG_W);
        #pragma unroll
        for (int ch = 0; ch < NCH; ch++)
            pv[ch] = in ? panb[ch*PL + yy*IMG_W + xx] : 0.f;
    }
    if (gcell >= 0) {
        int r = gcell / GW, c = gcell % GW;
        int yy = y0 - HG + r, xx = x0 - HG + c;
        bool in = ((unsigned)yy < IMG_H) && ((unsigned)xx < IMG_W);
        #pragma unroll
        for (int ch = 0; ch < NCH; ch++)
            uv[ch] = in ? ub[ch*PL + yy*IMG_W + xx] : 0.f;
    }

    if (tid < NCH*NCH)              wphi_s[tid] = Wphi[tid];
    else if (tid < 2*NCH*NCH)       wg_s[tid - NCH*NCH] = Wg[tid - NCH*NCH];
    __syncthreads();

    if (doPhi) {
        float po[NCH];
        #pragma unroll
        for (int o = 0; o < NCH; o++) {
            float acc = 0.f;
            #pragma unroll
            for (int ci = 0; ci < NCH; ci++)
                acc = fmaf(wphi_s[o*NCH+ci], pv[ci], acc);
            po[o] = acc;
        }
        phiA[phi_i] = make_float4(po[0], po[1], po[2], po[3]);
        phiB[phi_i] = make_float4(po[4], po[5], po[6], po[7]);
    }
    if (gcell >= 0) {
        float go[NCH];
        #pragma unroll
        for (int o = 0; o < NCH; o++) {
            float acc = 0.f;
            #pragma unroll
            for (int ci = 0; ci < NCH; ci++)
                acc = fmaf(wg_s[o*NCH+ci], uv[ci], acc);
            go[o] = acc;
        }
        gA[gcell] = make_float4(go[0], go[1], go[2], go[3]);
        gB[gcell] = make_float4(go[4], go[5], go[6], go[7]);
    }
    __syncthreads();

    const int px    = tid & (NPIX-1);
    const int slice = tid >> 7;            // owns offsets j = slice + 4k
    const int bar   = slice + 1;
    const int ty = px / TX, tx = px % TX;
    const int gy = y0 + ty, gx = x0 + tx;

    const int p0    = px;
    const int cell0 = (p0/CW + 3) * PW + (p0%CW + 3);
    const bool has1 = (px < CN - NPIX);
    const int p1    = px + NPIX;
    const int cell1 = has1 ? (p1/CW + 3) * PW + (p1%CW + 3) : cell0;

    unsigned long long v0p0, v0p1, v0p2, v0p3, v1p0, v1p1, v1p2, v1p3;
    {
        ulonglong2 a = *(const ulonglong2*)&phiA[cell0];
        ulonglong2 b = *(const ulonglong2*)&phiB[cell0];
        v0p0 = a.x; v0p1 = a.y; v0p2 = b.x; v0p3 = b.y;
        ulonglong2 a1 = *(const ulonglong2*)&phiA[cell1];
        ulonglong2 b1 = *(const ulonglong2*)&phiB[cell1];
        v1p0 = a1.x; v1p1 = a1.y; v1p2 = b1.x; v1p3 = b1.y;
    }

    float* Cme = Csb + slice * (KMAX*CNP);
    float* Hme = Hsb + slice * (KMAX*HN);

    // ---- produce all C maps for this slice ----
    #pragma unroll
    for (int k = 0; k < KMAX; k++) {
        const int j = slice + 4*k;
        if (j < 49) {
            const int dy = ((j * 9363) >> 16) - 3;
            const int dx = (j - (dy+3)*7) - 3;
            const int off = dy * PW + dx;
            {
                ulonglong2 wa = *(const ulonglong2*)&phiA[cell0 + off];
                ulonglong2 wb = *(const ulonglong2*)&phiB[cell0 + off];
                unsigned long long acc;
                MUL2(acc, v0p0, wa.x);
                FMA2(acc, v0p1, wa.y, acc);
                FMA2(acc, v0p2, wb.x, acc);
                FMA2(acc, v0p3, wb.y, acc);
                float lo, hi; UNPACK2(lo, hi, acc);
                Cme[k*CNP + p0] = lo + hi;
            }
            if (has1) {
                ulonglong2 wa = *(const ulonglong2*)&phiA[cell1 + off];
                ulonglong2 wb = *(const ulonglong2*)&phiB[cell1 + off];
                unsigned long long acc;
                MUL2(acc, v1p0, wa.x);
                FMA2(acc, v1p1, wa.y, acc);
                FMA2(acc, v1p2, wb.x, acc);
                FMA2(acc, v1p3, wb.y, acc);
                float lo, hi; UNPACK2(lo, hi, acc);
                Cme[k*CNP + p1] = lo + hi;
            }
        }
    }
    BARS(bar);     // slice-local: C produce -> H stage (H reads own slice only)

    // ---- H stage: horizontal 3-sums, pairs of columns ----
    #pragma unroll
    for (int i = 0; i < 9; i++) {
        const int uu = px + 128*i;
        if (uu < HUNITS) {
            const int k  = uu / HPAIRS;
            const int pr = uu - k*HPAIRS;
            const int r  = pr >> 3;
            const int c0 = (pr & 7) << 1;
            const float2 a = *(const float2*)&Cme[k*CNP + r*CW + c0];
            const float2 b = *(const float2*)&Cme[k*CNP + r*CW + c0 + 2];
            float h0 = a.x + a.y + b.x;
            float h1 = a.y + b.x + b.y;
            *(float2*)&Hme[k*HN + r*HW + c0] = make_float2(h0, h1);
        }
    }
    __syncthreads();   // full: all slices need slice0's H (k=6 <-> j=24, delta=0)

    // ---- per-pixel shift b = self-logit ||theta_q||^2 (box-sum of C_0) ----
    // slice 0 owns j=24 at k=6; its H map sits at Hsb + 6*HN.
    float b;
    {
        const float* h0 = &Hsb[6*HN + ty*HW + tx];
        b = h0[0] + h0[HW] + h0[2*HW];
    }

    // ---- single fused pass: logit -> exp(l-b) -> accumulate ----
    float S = 0.f;
    unsigned long long o01 = 0ULL, o23 = 0ULL, o45 = 0ULL, o67 = 0ULL;
    #pragma unroll
    for (int k = 0; k < KMAX; k++) {
        const int j = slice + 4*k;
        if (j < 49) {
            const int dy = ((j * 9363) >> 16) - 3;
            const int dx = (j - (dy+3)*7) - 3;
            const float* hb = &Hme[k*HN + ty*HW + tx];
            float v = hb[0] + hb[HW] + hb[2*HW];
            const bool in = ((unsigned)(gy+dy) < IMG_H) && ((unsigned)(gx+dx) < IMG_W);
            float l = in ? v : 0.f;       // double-unfold: OOB logit exactly 0
            float e = fexp(l - b);
            S += e;
            unsigned long long e2; PACK2(e2, e, e);
            const int gi = (ty + HG + dy) * GW + (tx + HG + dx);
            ulonglong2 g0 = *(const ulonglong2*)&gA[gi];
            ulonglong2 g1 = *(const ulonglong2*)&gB[gi];
            FMA2(o01, e2, g0.x, o01);
            FMA2(o23, e2, g0.y, o23);
            FMA2(o45, e2, g1.x, o45);
            FMA2(o67, e2, g1.y, o67);
        }
    }

    // ---- merge: plain sums across the 4 slices (common shift b) ----
    __syncthreads();                      // all slices done with Cs/Hs
    float o0,o1,o2,o3,o4,o5,o6,o7;
    UNPACK2(o0,o1,o01); UNPACK2(o2,o3,o23);
    UNPACK2(o4,o5,o45); UNPACK2(o6,o7,o67);
    float* red = Csb;                     // 9*512 = 4608 floats of scratch
    red[tid] = S;
    red[NTHREADS + 0*NTHREADS + tid] = o0;
    red[NTHREADS + 1*NTHREADS + tid] = o1;
    red[NTHREADS + 2*NTHREADS + tid] = o2;
    red[NTHREADS + 3*NTHREADS + tid] = o3;
    red[NTHREADS + 4*NTHREADS + tid] = o4;
    red[NTHREADS + 5*NTHREADS + tid] = o5;
    red[NTHREADS + 6*NTHREADS + tid] = o6;
    red[NTHREADS + 7*NTHREADS + tid] = o7;
    __syncthreads();

    {
        float St = red[0*NPIX + px] + red[1*NPIX + px]
                 + red[2*NPIX + px] + red[3*NPIX + px];
        float inv = 1.f / St;

        const int ch0 = 2*slice;          // each slice writes 2 channels
        float* ob = out + (size_t)bimg*NCH*PL + (size_t)gy*IMG_W + gx;
        #pragma unroll
        for (int cc = 0; cc < 2; cc++) {
            const int ch = ch0 + cc;
            const float* rc = red + NTHREADS + ch*NTHREADS + px;
            float v = rc[0*NPIX] + rc[1*NPIX] + rc[2*NPIX] + rc[3*NPIX];
            ob[ch*PL] = v * inv;
        }
    }
}

extern "C" void kernel_launch(void* const* d_in, const int* in_sizes, int n_in,
                              void* d_out, int out_size)
{
    const float* u    = (const float*)d_in[0];
    const float* pan  = (const float*)d_in[1];
    const float* Wphi = (const float*)d_in[2];
    const float* Wg   = (const float*)d_in[3];
    float* out = (float*)d_out;

    cudaFuncSetAttribute(attn_shift_kernel,
                         cudaFuncAttributeMaxDynamicSharedMemorySize, SMEM_TOTAL);

    dim3 grid(IMG_W / TX, IMG_H / TY, NB);   // (8, 16, 2) = 256 blocks
    dim3 block(NTHREADS);                     // 512
    attn_shift_kernel<<<grid, block, SMEM_TOTAL>>>(u, pan, Wphi, Wg, out);
}